// round 5
// baseline (speedup 1.0000x reference)
#include <cuda_runtime.h>

#define NQ 8
#define HD 256
#define S_TOT 8192
#define PAST 8191
#define HID 1536
#define INTER 6144
#define QDIM 2048
#define SCALE 0.0625f

// -------- scratch (device globals) --------
__device__ float g_qkv[2560];            // q[0:2048] (pre-scaled), k_new[2048:2304], v_new[2304:2560]
__device__ float g_scores[NQ * S_TOT];   // [h][s]
__device__ float g_part[128];            // per (head,slice) partial m [0:64], l [64:128]
__device__ float g_attn[QDIM];           // attention output (atomic accum)
__device__ float g_h1[HID];              // post-attention residual
__device__ float g_mid[INTER];           // gelu(gate)*up

static __device__ __forceinline__ float4 f4add(float4 a, float4 b) {
    a.x += b.x; a.y += b.y; a.z += b.z; a.w += b.w; return a;
}
static __device__ __forceinline__ void f4fma(float4& a, float s, float4 w) {
    a.x += s * w.x; a.y += s * w.y; a.z += s * w.z; a.w += s * w.w;
}
static __device__ __forceinline__ float gelu_exact(float v) {
    return 0.5f * v * (1.0f + erff(v * 0.70710678118654752f));
}

template<int PMIN>
static __device__ __forceinline__ float4 wred(float4 v) {
#pragma unroll
    for (int off = 16; off >= PMIN; off >>= 1) {
        v.x += __shfl_xor_sync(0xffffffffu, v.x, off);
        v.y += __shfl_xor_sync(0xffffffffu, v.y, off);
        v.z += __shfl_xor_sync(0xffffffffu, v.z, off);
        v.w += __shfl_xor_sync(0xffffffffu, v.w, off);
    }
    return v;
}

// ============ K1: QKV projection (+bias, q pre-scaled by SCALE) ============
// 320 blocks x 512 thr. Block owns 8 output cols; c4 = t&1 (32B/row), 256 rowgroups x 6 rows.
// Batched: all 6 weight float4s + 6 x scalars loaded before any FMA.
__global__ __launch_bounds__(512, 2) void k_qkv(
        const float* __restrict__ x,
        const float* __restrict__ Wq, const float* __restrict__ bq,
        const float* __restrict__ Wk, const float* __restrict__ bk,
        const float* __restrict__ Wv, const float* __restrict__ bv) {
    __shared__ float4 part[16 * 2];
    int t = threadIdx.x, lane = t & 31, wid = t >> 5;
    int c4 = t & 1, rg = t >> 1;
    int colBase = blockIdx.x * 8;
    const float* W; const float* bias; int ld, wcol; float sc;
    if (blockIdx.x < 256)      { W = Wq; bias = bq; ld = 2048; wcol = colBase;        sc = SCALE; }
    else if (blockIdx.x < 288) { W = Wk; bias = bk; ld = 256;  wcol = colBase - 2048; sc = 1.0f; }
    else                       { W = Wv; bias = bv; ld = 256;  wcol = colBase - 2304; sc = 1.0f; }
    const float* wp = W + wcol + c4 * 4;
    int r0 = rg * 6;
    float4 w[6]; float xs[6];
#pragma unroll
    for (int i = 0; i < 6; i++) w[i] = *(const float4*)(wp + (size_t)(r0 + i) * ld);
#pragma unroll
    for (int i = 0; i < 6; i++) xs[i] = __ldg(x + r0 + i);
    float4 acc = make_float4(0.f, 0.f, 0.f, 0.f);
#pragma unroll
    for (int i = 0; i < 6; i++) f4fma(acc, xs[i], w[i]);
    acc = wred<2>(acc);
    if (lane < 2) part[wid * 2 + lane] = acc;
    __syncthreads();
    if (t < 2) {
        float4 s = part[t];
#pragma unroll
        for (int wi = 1; wi < 16; wi++) s = f4add(s, part[wi * 2 + t]);
        int col = wcol + t * 4;
        float4 b = *(const float4*)(bias + col);
        s = f4add(s, b);
        s.x *= sc; s.y *= sc; s.z *= sc; s.w *= sc;
        *(float4*)&g_qkv[colBase + t * 4] = s;
    }
}

// ============ K2: scores[h][s] = q_h . K_s  (q already scaled) ============
// 512 blocks x 256 thr (8 warps). Warp handles 2 positions; all 4 K float4s batched up front.
__global__ __launch_bounds__(256, 2) void k_scores(const float* __restrict__ kp) {
    int t = threadIdx.x, lane = t & 31, wid = t >> 5;
    const float* q = g_qkv;
    float4 qa[8], qb[8];
#pragma unroll
    for (int h = 0; h < 8; h++) {
        qa[h] = *(const float4*)(q + h * 256 + lane * 8);
        qb[h] = *(const float4*)(q + h * 256 + lane * 8 + 4);
    }
    int gw = blockIdx.x * 8 + wid;          // 0..4095
    int s0 = gw, s1 = gw + 4096;
    const float* kr0 = (s0 < PAST) ? (kp + (size_t)s0 * 256) : (g_qkv + 2048);
    const float* kr1 = (s1 < PAST) ? (kp + (size_t)s1 * 256) : (g_qkv + 2048);
    float4 ka0 = *(const float4*)(kr0 + lane * 8);
    float4 kb0 = *(const float4*)(kr0 + lane * 8 + 4);
    float4 ka1 = *(const float4*)(kr1 + lane * 8);
    float4 kb1 = *(const float4*)(kr1 + lane * 8 + 4);
#pragma unroll
    for (int it = 0; it < 2; it++) {
        float4 ka = it ? ka1 : ka0;
        float4 kb = it ? kb1 : kb0;
        int s = it ? s1 : s0;
        float acc[8];
#pragma unroll
        for (int h = 0; h < 8; h++) {
            acc[h] = qa[h].x * ka.x + qa[h].y * ka.y + qa[h].z * ka.z + qa[h].w * ka.w
                   + qb[h].x * kb.x + qb[h].y * kb.y + qb[h].z * kb.z + qb[h].w * kb.w;
        }
#pragma unroll
        for (int h = 0; h < 8; h++) {
#pragma unroll
            for (int off = 16; off; off >>= 1)
                acc[h] += __shfl_xor_sync(0xffffffffu, acc[h], off);
        }
#pragma unroll
        for (int h = 0; h < 8; h++)
            if (lane == h) g_scores[h * S_TOT + s] = acc[h];
    }
}

// ============ K3: partial softmax stats per (head, slice of 1024); zero g_attn ====
__global__ __launch_bounds__(256) void k_stats() {
    __shared__ float sm_m[256], sm_l[256];
    int bb = blockIdx.x, t = threadIdx.x;
    int h = bb >> 3, sl = bb & 7;
    const float* sc = g_scores + h * S_TOT + sl * 1024;
    float4 a = *(const float4*)(sc + t * 4);
    float m = fmaxf(fmaxf(a.x, a.y), fmaxf(a.z, a.w));
    float l = __expf(a.x - m) + __expf(a.y - m) + __expf(a.z - m) + __expf(a.w - m);
    sm_m[t] = m; sm_l[t] = l;
    __syncthreads();
    for (int s = 128; s >= 1; s >>= 1) {
        if (t < s) {
            float m1 = sm_m[t], l1 = sm_l[t];
            float m2 = sm_m[t + s], l2 = sm_l[t + s];
            float nm = fmaxf(m1, m2);
            sm_l[t] = l1 * __expf(m1 - nm) + l2 * __expf(m2 - nm);
            sm_m[t] = nm;
        }
        __syncthreads();
    }
    if (t == 0) { g_part[bb] = sm_m[0]; g_part[64 + bb] = sm_l[0]; }
    if (bb < 8) g_attn[bb * 256 + t] = 0.0f;
}

// ============ K4: out[h][d] += sum_s p[h][s] * V[s][d] ============
// 512 blocks x 256 thr, 16 positions/block. Thread owns (head-pair, d4).
// Two batches of 8 V-rows loaded into registers before the FMAs -> MLP=8.
__global__ __launch_bounds__(256, 3) void k_av(const float* __restrict__ vp) {
    __shared__ float p_sm[16][8];
    __shared__ float s_m[8], s_il[8];
    int t = threadIdx.x;
    int sBase = blockIdx.x * 16;
    if (t < 8) {
        float m = g_part[t * 8], l = g_part[64 + t * 8];
#pragma unroll
        for (int i = 1; i < 8; i++) {
            float m2 = g_part[t * 8 + i], l2 = g_part[64 + t * 8 + i];
            float nm = fmaxf(m, m2);
            l = l * __expf(m - nm) + l2 * __expf(m2 - nm);
            m = nm;
        }
        s_m[t] = m; s_il[t] = 1.0f / l;
    }
    __syncthreads();
    if (t < 128) {
        int pos = t >> 3, h = t & 7;
        p_sm[pos][h] = __expf(g_scores[h * S_TOT + sBase + pos] - s_m[h]) * s_il[h];
    }
    __syncthreads();
    int d4 = t & 63, hp = t >> 6;
    int h0 = hp * 2, h1 = h0 + 1;
    float4 acc0 = make_float4(0.f, 0.f, 0.f, 0.f);
    float4 acc1 = make_float4(0.f, 0.f, 0.f, 0.f);
#pragma unroll
    for (int b = 0; b < 2; b++) {
        float4 v[8];
#pragma unroll
        for (int j = 0; j < 8; j++) {
            int s = sBase + b * 8 + j;
            const float* vrow = (s < PAST) ? (vp + (size_t)s * 256) : (g_qkv + 2304);
            v[j] = *(const float4*)(vrow + d4 * 4);
        }
#pragma unroll
        for (int j = 0; j < 8; j++) {
            f4fma(acc0, p_sm[b * 8 + j][h0], v[j]);
            f4fma(acc1, p_sm[b * 8 + j][h1], v[j]);
        }
    }
    float4* attn4 = (float4*)g_attn;
    atomicAdd(&attn4[h0 * 64 + d4], acc0);
    atomicAdd(&attn4[h1 * 64 + d4], acc1);
}

// ============ K5: h1 = x + attn @ Wo + bo ============
// 192 blocks x 512 thr; 8 rows/thread, all batched.
__global__ __launch_bounds__(512, 2) void k_wo(
        const float* __restrict__ x,
        const float* __restrict__ Wo, const float* __restrict__ bo) {
    __shared__ float4 part[16 * 2];
    int t = threadIdx.x, lane = t & 31, wid = t >> 5;
    int c4 = t & 1, rg = t >> 1;
    int colBase = blockIdx.x * 8;
    const float* wp = Wo + colBase + c4 * 4;
    int r0 = rg * 8;
    float4 w[8]; float xs[8];
#pragma unroll
    for (int i = 0; i < 8; i++) w[i] = *(const float4*)(wp + (size_t)(r0 + i) * 1536);
#pragma unroll
    for (int i = 0; i < 8; i++) xs[i] = g_attn[r0 + i];
    float4 acc = make_float4(0.f, 0.f, 0.f, 0.f);
#pragma unroll
    for (int i = 0; i < 8; i++) f4fma(acc, xs[i], w[i]);
    acc = wred<2>(acc);
    if (lane < 2) part[wid * 2 + lane] = acc;
    __syncthreads();
    if (t < 2) {
        float4 s = part[t];
#pragma unroll
        for (int wi = 1; wi < 16; wi++) s = f4add(s, part[wi * 2 + t]);
        int col = colBase + t * 4;
        s = f4add(s, *(const float4*)(bo + col));
        s = f4add(s, *(const float4*)(x + col));
        *(float4*)&g_h1[col] = s;
    }
}

// ============ K6: mid = gelu(h1@Wg+bg) * (h1@Wu+bu) ============
// 384 blocks x 512 thr. Block owns 16 cols of both; 12 rows/thread in 3 batches of 4
// (8 float4 loads in flight per batch; keeps regs <= 64 for 2 blocks/SM).
__global__ __launch_bounds__(512, 2) void k_gateup(
        const float* __restrict__ Wg, const float* __restrict__ bg,
        const float* __restrict__ Wu, const float* __restrict__ bu) {
    __shared__ float4 pg[16 * 4], pu[16 * 4];
    int t = threadIdx.x, lane = t & 31, wid = t >> 5;
    int c4 = t & 3, rg = t >> 2;
    int colBase = blockIdx.x * 16;
    const float* wg = Wg + colBase + c4 * 4;
    const float* wu = Wu + colBase + c4 * 4;
    float4 ag = make_float4(0.f, 0.f, 0.f, 0.f);
    float4 au = make_float4(0.f, 0.f, 0.f, 0.f);
    int r0 = rg * 12;
#pragma unroll
    for (int b = 0; b < 3; b++) {
        float4 wa[4], wb[4]; float xs[4];
#pragma unroll
        for (int i = 0; i < 4; i++) {
            int r = r0 + b * 4 + i;
            wa[i] = *(const float4*)(wg + (size_t)r * 6144);
            wb[i] = *(const float4*)(wu + (size_t)r * 6144);
        }
#pragma unroll
        for (int i = 0; i < 4; i++) xs[i] = g_h1[r0 + b * 4 + i];
#pragma unroll
        for (int i = 0; i < 4; i++) { f4fma(ag, xs[i], wa[i]); f4fma(au, xs[i], wb[i]); }
    }
    ag = wred<4>(ag);
    au = wred<4>(au);
    if (lane < 4) { pg[wid * 4 + lane] = ag; pu[wid * 4 + lane] = au; }
    __syncthreads();
    if (t < 4) {
        float4 sg = pg[t], su = pu[t];
#pragma unroll
        for (int wi = 1; wi < 16; wi++) { sg = f4add(sg, pg[wi * 4 + t]); su = f4add(su, pu[wi * 4 + t]); }
        int col = colBase + t * 4;
        float4 gv = f4add(sg, *(const float4*)(bg + col));
        float4 uv = f4add(su, *(const float4*)(bu + col));
        float4 o;
        o.x = gelu_exact(gv.x) * uv.x;
        o.y = gelu_exact(gv.y) * uv.y;
        o.z = gelu_exact(gv.z) * uv.z;
        o.w = gelu_exact(gv.w) * uv.w;
        *(float4*)&g_mid[col] = o;
    }
}

// ============ K7: out = h1 + mid @ Wd + bd ============
// 192 blocks x 512 thr; 24 rows/thread in 3 batches of 8.
__global__ __launch_bounds__(512, 2) void k_down(
        const float* __restrict__ Wd, const float* __restrict__ bd,
        float* __restrict__ out) {
    __shared__ float4 part[16 * 2];
    int t = threadIdx.x, lane = t & 31, wid = t >> 5;
    int c4 = t & 1, rg = t >> 1;
    int colBase = blockIdx.x * 8;
    const float* wp = Wd + colBase + c4 * 4;
    float4 acc = make_float4(0.f, 0.f, 0.f, 0.f);
    int r0 = rg * 24;
#pragma unroll
    for (int b = 0; b < 3; b++) {
        float4 w[8]; float xs[8];
#pragma unroll
        for (int i = 0; i < 8; i++)
            w[i] = *(const float4*)(wp + (size_t)(r0 + b * 8 + i) * 1536);
#pragma unroll
        for (int i = 0; i < 8; i++) xs[i] = g_mid[r0 + b * 8 + i];
#pragma unroll
        for (int i = 0; i < 8; i++) f4fma(acc, xs[i], w[i]);
    }
    acc = wred<2>(acc);
    if (lane < 2) part[wid * 2 + lane] = acc;
    __syncthreads();
    if (t < 2) {
        float4 s = part[t];
#pragma unroll
        for (int wi = 1; wi < 16; wi++) s = f4add(s, part[wi * 2 + t]);
        int col = colBase + t * 4;
        s = f4add(s, *(const float4*)(bd + col));
        s = f4add(s, *(const float4*)&g_h1[col]);
        *(float4*)&out[col] = s;
    }
}

extern "C" void kernel_launch(void* const* d_in, const int* in_sizes, int n_in,
                              void* d_out, int out_size) {
    const float* x  = (const float*)d_in[0];
    const float* kp = (const float*)d_in[1];
    const float* vp = (const float*)d_in[2];
    const float* Wq = (const float*)d_in[3];
    const float* bq = (const float*)d_in[4];
    const float* Wk = (const float*)d_in[5];
    const float* bk = (const float*)d_in[6];
    const float* Wv = (const float*)d_in[7];
    const float* bv = (const float*)d_in[8];
    const float* Wo = (const float*)d_in[9];
    const float* bo = (const float*)d_in[10];
    const float* Wg = (const float*)d_in[11];
    const float* bg = (const float*)d_in[12];
    const float* Wu = (const float*)d_in[13];
    const float* bu = (const float*)d_in[14];
    const float* Wd = (const float*)d_in[15];
    const float* bd = (const float*)d_in[16];

    k_qkv   <<<320, 512>>>(x, Wq, bq, Wk, bk, Wv, bv);
    k_scores<<<512, 256>>>(kp);
    k_stats <<<64,  256>>>();
    k_av    <<<512, 256>>>(vp);
    k_wo    <<<192, 512>>>(x, Wo, bo);
    k_gateup<<<384, 512>>>(Wg, bg, Wu, bu);
    k_down  <<<192, 512>>>(Wd, bd, (float*)d_out);
}

// round 6
// speedup vs baseline: 1.2975x; 1.2975x over previous
#include <cuda_runtime.h>

#define NQ 8
#define HD 256
#define S_TOT 8192
#define PAST 8191
#define HID 1536
#define INTER 6144
#define QDIM 2048
#define SCALE 0.0625f
#define NCHUNK 256          // 8192 / 32
#define CHUNK 32

// -------- scratch (device globals) --------
__device__ float g_qkv[2560];              // q[0:2048] (pre-scaled), k_new[2048:2304], v_new[2304:2560]
__device__ float g_avpart[NCHUNK * 2048];  // per-chunk partial AV: [c][h*256+d]
__device__ float g_stm[NCHUNK * 8];        // per-(chunk,head) local max
__device__ float g_stl[NCHUNK * 8];        // per-(chunk,head) local sum
__device__ float g_attn[QDIM];             // final attention output
__device__ float g_h1[HID];                // post-attention residual
__device__ float g_mid[INTER];             // gelu(gate)*up

static __device__ __forceinline__ float4 f4add(float4 a, float4 b) {
    a.x += b.x; a.y += b.y; a.z += b.z; a.w += b.w; return a;
}
static __device__ __forceinline__ void f4fma(float4& a, float s, float4 w) {
    a.x += s * w.x; a.y += s * w.y; a.z += s * w.z; a.w += s * w.w;
}
static __device__ __forceinline__ float gelu_exact(float v) {
    return 0.5f * v * (1.0f + erff(v * 0.70710678118654752f));
}
template<int PMIN>
static __device__ __forceinline__ float4 wred(float4 v) {
#pragma unroll
    for (int off = 16; off >= PMIN; off >>= 1) {
        v.x += __shfl_xor_sync(0xffffffffu, v.x, off);
        v.y += __shfl_xor_sync(0xffffffffu, v.y, off);
        v.z += __shfl_xor_sync(0xffffffffu, v.z, off);
        v.w += __shfl_xor_sync(0xffffffffu, v.w, off);
    }
    return v;
}

// ============ K1: QKV projection (+bias, q pre-scaled by SCALE) ============ (R3 version)
__global__ __launch_bounds__(512) void k_qkv(
        const float* __restrict__ x,
        const float* __restrict__ Wq, const float* __restrict__ bq,
        const float* __restrict__ Wk, const float* __restrict__ bk,
        const float* __restrict__ Wv, const float* __restrict__ bv) {
    __shared__ float4 part[16 * 2];
    int t = threadIdx.x, lane = t & 31, wid = t >> 5;
    int c4 = t & 1, rg = t >> 1;
    int colBase = blockIdx.x * 8;
    const float* W; const float* bias; int ld, wcol; float sc;
    if (blockIdx.x < 256)      { W = Wq; bias = bq; ld = 2048; wcol = colBase;        sc = SCALE; }
    else if (blockIdx.x < 288) { W = Wk; bias = bk; ld = 256;  wcol = colBase - 2048; sc = 1.0f; }
    else                       { W = Wv; bias = bv; ld = 256;  wcol = colBase - 2304; sc = 1.0f; }
    const float* wp = W + wcol + c4 * 4;
    float4 acc = make_float4(0.f, 0.f, 0.f, 0.f);
    int r0 = rg * 6;
#pragma unroll
    for (int i = 0; i < 6; i++) {
        int r = r0 + i;
        float xv = __ldg(x + r);
        float4 w = *(const float4*)(wp + (size_t)r * ld);
        f4fma(acc, xv, w);
    }
    acc = wred<2>(acc);
    if (lane < 2) part[wid * 2 + lane] = acc;
    __syncthreads();
    if (t < 2) {
        float4 s = part[t];
#pragma unroll
        for (int w = 1; w < 16; w++) s = f4add(s, part[w * 2 + t]);
        int col = wcol + t * 4;
        float4 b = *(const float4*)(bias + col);
        s = f4add(s, b);
        s.x *= sc; s.y *= sc; s.z *= sc; s.w *= sc;
        *(float4*)&g_qkv[colBase + t * 4] = s;
    }
}

// ============ K2: fused flash-decode partial ============
// 256 blocks x 256 thr. Block = chunk of 32 KV rows. Phase1: scores (warp per
// 4 rows, all 8 heads). Phase2: local softmax (m,l per head). Phase3: p.V with
// 8 head-accumulators and 8 V loads in flight; block writes private partial.
__global__ __launch_bounds__(256, 2) void k_attn(
        const float* __restrict__ kp, const float* __restrict__ vp) {
    __shared__ float s_sm[8][CHUNK];          // scores then p
    __shared__ float4 red[4 * 8 * 64];        // 32KB group staging
    int t = threadIdx.x, lane = t & 31, wid = t >> 5;
    int c = blockIdx.x;
    int sBase = c * CHUNK;

    // q for all 8 heads (pre-scaled)
    float4 qa[8], qb[8];
#pragma unroll
    for (int h = 0; h < 8; h++) {
        qa[h] = *(const float4*)(g_qkv + h * 256 + lane * 8);
        qb[h] = *(const float4*)(g_qkv + h * 256 + lane * 8 + 4);
    }
    // ---- Phase 1: scores; warp wid handles rows wid*4 .. wid*4+3 (2 at a time)
#pragma unroll
    for (int it = 0; it < 2; it++) {
        int r0 = sBase + wid * 4 + it * 2;
        int r1 = r0 + 1;
        const float* kr0 = (r0 < PAST) ? (kp + (size_t)r0 * 256) : (g_qkv + 2048);
        const float* kr1 = (r1 < PAST) ? (kp + (size_t)r1 * 256) : (g_qkv + 2048);
        float4 ka0 = *(const float4*)(kr0 + lane * 8);
        float4 kb0 = *(const float4*)(kr0 + lane * 8 + 4);
        float4 ka1 = *(const float4*)(kr1 + lane * 8);
        float4 kb1 = *(const float4*)(kr1 + lane * 8 + 4);
        float a0[8], a1[8];
#pragma unroll
        for (int h = 0; h < 8; h++) {
            a0[h] = qa[h].x * ka0.x + qa[h].y * ka0.y + qa[h].z * ka0.z + qa[h].w * ka0.w
                  + qb[h].x * kb0.x + qb[h].y * kb0.y + qb[h].z * kb0.z + qb[h].w * kb0.w;
            a1[h] = qa[h].x * ka1.x + qa[h].y * ka1.y + qa[h].z * ka1.z + qa[h].w * ka1.w
                  + qb[h].x * kb1.x + qb[h].y * kb1.y + qb[h].z * kb1.z + qb[h].w * kb1.w;
        }
#pragma unroll
        for (int h = 0; h < 8; h++) {
#pragma unroll
            for (int off = 16; off; off >>= 1) {
                a0[h] += __shfl_xor_sync(0xffffffffu, a0[h], off);
                a1[h] += __shfl_xor_sync(0xffffffffu, a1[h], off);
            }
        }
        if (lane < 8) {
            s_sm[lane][wid * 4 + it * 2]     = a0[lane];
            s_sm[lane][wid * 4 + it * 2 + 1] = a1[lane];
        }
    }
    __syncthreads();
    // ---- Phase 2: per-head local softmax; warp wid = head wid
    {
        float s = s_sm[wid][lane];
        float m = s;
#pragma unroll
        for (int off = 16; off; off >>= 1) m = fmaxf(m, __shfl_xor_sync(0xffffffffu, m, off));
        float p = __expf(s - m);
        float l = p;
#pragma unroll
        for (int off = 16; off; off >>= 1) l += __shfl_xor_sync(0xffffffffu, l, off);
        s_sm[wid][lane] = p;
        if (lane == 0) { g_stm[c * 8 + wid] = m; g_stl[c * 8 + wid] = l; }
    }
    __syncthreads();
    // ---- Phase 3: p.V — thread (group g of 8 positions, d4)
    int d4 = t & 63, g = t >> 6;
    float4 acc[8];
#pragma unroll
    for (int h = 0; h < 8; h++) acc[h] = make_float4(0.f, 0.f, 0.f, 0.f);
    float4 v[8];
#pragma unroll
    for (int j = 0; j < 8; j++) {
        int s = sBase + g * 8 + j;
        const float* vrow = (s < PAST) ? (vp + (size_t)s * 256) : (g_qkv + 2304);
        v[j] = *(const float4*)(vrow + d4 * 4);
    }
#pragma unroll
    for (int j = 0; j < 8; j++) {
        int pos = g * 8 + j;
#pragma unroll
        for (int h = 0; h < 8; h++) f4fma(acc[h], s_sm[h][pos], v[j]);
    }
#pragma unroll
    for (int h = 0; h < 8; h++) red[g * 512 + h * 64 + d4] = acc[h];
    __syncthreads();
    float4* outp = (float4*)(g_avpart + (size_t)c * 2048);
#pragma unroll
    for (int k = 0; k < 2; k++) {
        int o = t + k * 256;
        float4 s = f4add(f4add(red[o], red[512 + o]), f4add(red[1024 + o], red[1536 + o]));
        outp[o] = s;
    }
}

// ============ K3: combine partials -> g_attn ============
// 16 blocks x 256 thr. Block handles 32 float4 outputs; thread = (output, chunk-slice of 32).
__global__ __launch_bounds__(256) void k_comb() {
    __shared__ float w_sm[NCHUNK * 8];    // weight e^{m_c-M_h}/L_h, [c][h] : 8KB
    __shared__ float4 red2[256];
    int t = threadIdx.x, lane = t & 31, wid = t >> 5;
    // per-head M then L (warp wid = head wid); each lane covers 8 chunks
    float mv[8], lv[8];
#pragma unroll
    for (int i = 0; i < 8; i++) {
        int c = lane * 8 + i;
        mv[i] = g_stm[c * 8 + wid];
        lv[i] = g_stl[c * 8 + wid];
    }
    float M = mv[0];
#pragma unroll
    for (int i = 1; i < 8; i++) M = fmaxf(M, mv[i]);
#pragma unroll
    for (int off = 16; off; off >>= 1) M = fmaxf(M, __shfl_xor_sync(0xffffffffu, M, off));
    float L = 0.f;
#pragma unroll
    for (int i = 0; i < 8; i++) L += __expf(mv[i] - M) * lv[i];
#pragma unroll
    for (int off = 16; off; off >>= 1) L += __shfl_xor_sync(0xffffffffu, L, off);
    float invL = 1.0f / L;
#pragma unroll
    for (int i = 0; i < 8; i++) {
        int c = lane * 8 + i;
        w_sm[c * 8 + wid] = __expf(mv[i] - M) * invL;
    }
    __syncthreads();
    // main accumulate: o = global float4 output index, h = o>>6
    int oLoc = t >> 3, sl = t & 7;
    int o = blockIdx.x * 32 + oLoc;
    int h = o >> 6;
    float4 acc = make_float4(0.f, 0.f, 0.f, 0.f);
#pragma unroll
    for (int b = 0; b < 4; b++) {
        float4 vv[8];
#pragma unroll
        for (int i = 0; i < 8; i++) {
            int c = sl * 32 + b * 8 + i;
            vv[i] = *(const float4*)(g_avpart + (size_t)c * 2048 + o * 4);
        }
#pragma unroll
        for (int i = 0; i < 8; i++) {
            int c = sl * 32 + b * 8 + i;
            f4fma(acc, w_sm[c * 8 + h], vv[i]);
        }
    }
    red2[t] = acc;
    __syncthreads();
    if (t < 32) {
        float4 s = red2[t * 8];
#pragma unroll
        for (int i = 1; i < 8; i++) s = f4add(s, red2[t * 8 + i]);
        ((float4*)g_attn)[blockIdx.x * 32 + t] = s;
    }
}

// ============ K5: h1 = x + attn @ Wo + bo ============ (R3 version)
__global__ __launch_bounds__(512) void k_wo(
        const float* __restrict__ x,
        const float* __restrict__ Wo, const float* __restrict__ bo) {
    __shared__ float4 part[16 * 2];
    int t = threadIdx.x, lane = t & 31, wid = t >> 5;
    int c4 = t & 1, rg = t >> 1;
    int colBase = blockIdx.x * 8;
    const float* wp = Wo + colBase + c4 * 4;
    float4 acc = make_float4(0.f, 0.f, 0.f, 0.f);
    int r0 = rg * 8;
#pragma unroll
    for (int i = 0; i < 8; i++) {
        int r = r0 + i;
        float xv = g_attn[r];
        float4 w = *(const float4*)(wp + (size_t)r * 1536);
        f4fma(acc, xv, w);
    }
    acc = wred<2>(acc);
    if (lane < 2) part[wid * 2 + lane] = acc;
    __syncthreads();
    if (t < 2) {
        float4 s = part[t];
#pragma unroll
        for (int w = 1; w < 16; w++) s = f4add(s, part[w * 2 + t]);
        int col = colBase + t * 4;
        s = f4add(s, *(const float4*)(bo + col));
        s = f4add(s, *(const float4*)(x + col));
        *(float4*)&g_h1[col] = s;
    }
}

// ============ K6: mid = gelu(h1@Wg+bg) * (h1@Wu+bu) ============ (R3 version)
__global__ __launch_bounds__(512) void k_gateup(
        const float* __restrict__ Wg, const float* __restrict__ bg,
        const float* __restrict__ Wu, const float* __restrict__ bu) {
    __shared__ float4 pg[16 * 4], pu[16 * 4];
    int t = threadIdx.x, lane = t & 31, wid = t >> 5;
    int c4 = t & 3, rg = t >> 2;
    int colBase = blockIdx.x * 16;
    const float* wg = Wg + colBase + c4 * 4;
    const float* wu = Wu + colBase + c4 * 4;
    float4 ag = make_float4(0.f, 0.f, 0.f, 0.f);
    float4 au = make_float4(0.f, 0.f, 0.f, 0.f);
    int r0 = rg * 12;
#pragma unroll
    for (int i = 0; i < 12; i++) {
        int r = r0 + i;
        float xv = g_h1[r];
        float4 a = *(const float4*)(wg + (size_t)r * 6144);
        float4 b = *(const float4*)(wu + (size_t)r * 6144);
        f4fma(ag, xv, a);
        f4fma(au, xv, b);
    }
    ag = wred<4>(ag);
    au = wred<4>(au);
    if (lane < 4) { pg[wid * 4 + lane] = ag; pu[wid * 4 + lane] = au; }
    __syncthreads();
    if (t < 4) {
        float4 sg = pg[t], su = pu[t];
#pragma unroll
        for (int w = 1; w < 16; w++) { sg = f4add(sg, pg[w * 4 + t]); su = f4add(su, pu[w * 4 + t]); }
        int col = colBase + t * 4;
        float4 gv = f4add(sg, *(const float4*)(bg + col));
        float4 uv = f4add(su, *(const float4*)(bu + col));
        float4 o;
        o.x = gelu_exact(gv.x) * uv.x;
        o.y = gelu_exact(gv.y) * uv.y;
        o.z = gelu_exact(gv.z) * uv.z;
        o.w = gelu_exact(gv.w) * uv.w;
        *(float4*)&g_mid[col] = o;
    }
}

// ============ K7: out = h1 + mid @ Wd + bd ============ (R3 version)
__global__ __launch_bounds__(512) void k_down(
        const float* __restrict__ Wd, const float* __restrict__ bd,
        float* __restrict__ out) {
    __shared__ float4 part[16 * 2];
    int t = threadIdx.x, lane = t & 31, wid = t >> 5;
    int c4 = t & 1, rg = t >> 1;
    int colBase = blockIdx.x * 8;
    const float* wp = Wd + colBase + c4 * 4;
    float4 acc = make_float4(0.f, 0.f, 0.f, 0.f);
    int r0 = rg * 24;
#pragma unroll 12
    for (int i = 0; i < 24; i++) {
        int r = r0 + i;
        float xv = g_mid[r];
        float4 w = *(const float4*)(wp + (size_t)r * 1536);
        f4fma(acc, xv, w);
    }
    acc = wred<2>(acc);
    if (lane < 2) part[wid * 2 + lane] = acc;
    __syncthreads();
    if (t < 2) {
        float4 s = part[t];
#pragma unroll
        for (int w = 1; w < 16; w++) s = f4add(s, part[w * 2 + t]);
        int col = colBase + t * 4;
        s = f4add(s, *(const float4*)(bd + col));
        s = f4add(s, *(const float4*)&g_h1[col]);
        *(float4*)&out[col] = s;
    }
}

extern "C" void kernel_launch(void* const* d_in, const int* in_sizes, int n_in,
                              void* d_out, int out_size) {
    const float* x  = (const float*)d_in[0];
    const float* kp = (const float*)d_in[1];
    const float* vp = (const float*)d_in[2];
    const float* Wq = (const float*)d_in[3];
    const float* bq = (const float*)d_in[4];
    const float* Wk = (const float*)d_in[5];
    const float* bk = (const float*)d_in[6];
    const float* Wv = (const float*)d_in[7];
    const float* bv = (const float*)d_in[8];
    const float* Wo = (const float*)d_in[9];
    const float* bo = (const float*)d_in[10];
    const float* Wg = (const float*)d_in[11];
    const float* bg = (const float*)d_in[12];
    const float* Wu = (const float*)d_in[13];
    const float* bu = (const float*)d_in[14];
    const float* Wd = (const float*)d_in[15];
    const float* bd = (const float*)d_in[16];

    k_qkv   <<<320, 512>>>(x, Wq, bq, Wk, bk, Wv, bv);
    k_attn  <<<256, 256>>>(kp, vp);
    k_comb  <<<16,  256>>>();
    k_wo    <<<192, 512>>>(x, Wo, bo);
    k_gateup<<<384, 512>>>(Wg, bg, Wu, bu);
    k_down  <<<192, 512>>>(Wd, bd, (float*)d_out);
}